// round 8
// baseline (speedup 1.0000x reference)
#include <cuda_runtime.h>

#define NN 8192
#define DD 64
#define BM 64
#define BN 64
#define TM 4
#define TN 8
#define JSPLIT 8
#define JCHUNK (NN / JSPLIT)
#define NTHREADS 128
#define NBLOCKS ((NN / BM) * JSPLIT)   // 1024
#define EPSF 1e-7f
#define LN2F 0.69314718055994530942f

// ---------------- scratch (device globals; no allocation) ----------------
__device__ float        g_s_part[JSPLIT][NN];   // sum exp(-d), j != i (partial)
__device__ float        g_S_part[JSPLIT][NN];   // sum d over positives (partial)
__device__ int          g_P_part[JSPLIT][NN];   // positive count (partial)
__device__ unsigned int g_counter;              // last-block detector (BSS = 0)

// ---------------- single fused kernel ----------------
__global__ void __launch_bounds__(NTHREADS)
hyper_kernel(const float* __restrict__ pts, const long long* __restrict__ labels,
             float* __restrict__ out)
{
    __shared__ __align__(16) float As[DD][BM + 4];   // [k][row], padded stride 68
    __shared__ __align__(16) float Bs[DD][BN + 4];   // [k][col]
    __shared__ float s_sqc[BN], s_wc[BN];
    __shared__ int   s_lc[BN];
    __shared__ float s_sqr[BM], s_wr[BM];
    __shared__ double s_red[NTHREADS / 32];
    __shared__ unsigned int s_last;

    const int tid  = threadIdx.x;
    const int tx   = tid & 7;    // 8 col-groups
    const int ty   = tid >> 3;   // 16 row-groups
    const int row0 = blockIdx.x * BM;
    const int jc   = blockIdx.y;
    const int jbeg = jc * JCHUNK;
    const int jend = jbeg + JCHUNK;

    // ---- load A tile, transposed to [k][row] ----
    for (int it = tid; it < BM * (DD / 4); it += NTHREADS) {
        int r  = it >> 4;      // DD/4 == 16
        int c4 = it & 15;
        float4 v = *reinterpret_cast<const float4*>(pts + (size_t)(row0 + r) * DD + c4 * 4);
        As[c4 * 4 + 0][r] = v.x;
        As[c4 * 4 + 1][r] = v.y;
        As[c4 * 4 + 2][r] = v.z;
        As[c4 * 4 + 3][r] = v.w;
    }
    __syncthreads();

    // ---- per-row norms/weights from the A tile (fused former prep) ----
    if (tid < BM) {
        float sq = 0.f;
#pragma unroll
        for (int k = 0; k < DD; k++) sq = fmaf(As[k][tid], As[k][tid], sq);
        s_sqr[tid] = sq;
        s_wr[tid]  = 1.0f / (1.0f - sq);   // norms < 0.9 by construction
    }
    __syncthreads();

    int   gr[TM];  float sqr[TM], wr2[TM];  int lr[TM];
#pragma unroll
    for (int m = 0; m < TM; m++) {
        int r  = ty * TM + m;
        gr[m]  = row0 + r;
        sqr[m] = s_sqr[r];
        wr2[m] = 2.0f * s_wr[r];
        lr[m]  = (int)labels[row0 + r];
    }

    float s_acc[TM] = {0.f, 0.f, 0.f, 0.f};
    float S_acc[TM] = {0.f, 0.f, 0.f, 0.f};   // sum of log2(1+z) over positives
    int   P_acc[TM] = {0, 0, 0, 0};

    for (int jt = jbeg; jt < jend; jt += BN) {
        __syncthreads();   // protect Bs / s_* from previous iteration's readers
        if (tid < BN) {
            int j = jt + tid;
            const float4* p = reinterpret_cast<const float4*>(pts + (size_t)j * DD);
            float sq = 0.f;
#pragma unroll
            for (int c4 = 0; c4 < DD / 4; c4++) {
                float4 v = p[c4];
                Bs[c4 * 4 + 0][tid] = v.x;
                Bs[c4 * 4 + 1][tid] = v.y;
                Bs[c4 * 4 + 2][tid] = v.z;
                Bs[c4 * 4 + 3][tid] = v.w;
                sq = fmaf(v.x, v.x, fmaf(v.y, v.y, fmaf(v.z, v.z, fmaf(v.w, v.w, sq))));
            }
            s_sqc[tid] = sq;
            s_wc[tid]  = 1.0f / (1.0f - sq);
            s_lc[tid]  = (int)labels[j];
        }
        __syncthreads();

        float acc[TM][TN];
#pragma unroll
        for (int m = 0; m < TM; m++)
#pragma unroll
            for (int c = 0; c < TN; c++) acc[m][c] = 0.f;

#pragma unroll 8
        for (int k = 0; k < DD; k++) {
            // conflict-free: A broadcast; B split as tx*4 and 32+tx*4 tiles all 32 banks
            float4 a  = *reinterpret_cast<const float4*>(&As[k][ty * TM]);
            float4 b0 = *reinterpret_cast<const float4*>(&Bs[k][tx * 4]);
            float4 b1 = *reinterpret_cast<const float4*>(&Bs[k][32 + tx * 4]);
            float av[TM] = {a.x, a.y, a.z, a.w};
            float bv[TN] = {b0.x, b0.y, b0.z, b0.w, b1.x, b1.y, b1.z, b1.w};
#pragma unroll
            for (int m = 0; m < TM; m++)
#pragma unroll
                for (int c = 0; c < TN; c++)
                    acc[m][c] = fmaf(av[m], bv[c], acc[m][c]);
        }

        // ---- epilogue: hyperbolic distance + online accumulators ----
        int jj[TN];
#pragma unroll
        for (int c = 0; c < TN; c++)
            jj[c] = (c < 4) ? (tx * 4 + c) : (32 + tx * 4 + (c - 4));

        float sqcv[TN], wcv[TN]; int lcv[TN], gjv[TN];
#pragma unroll
        for (int c = 0; c < TN; c++) {
            sqcv[c] = s_sqc[jj[c]];
            wcv[c]  = s_wc[jj[c]];
            lcv[c]  = s_lc[jj[c]];
            gjv[c]  = jt + jj[c];
        }

#pragma unroll
        for (int m = 0; m < TM; m++) {
            float sloc = 0.f, Sloc = 0.f; int Ploc = 0;
#pragma unroll
            for (int c = 0; c < TN; c++) {
                float dot = acc[m][c];
                float sqd = fmaxf(fmaf(-2.0f, dot, sqr[m] + sqcv[c]), 0.0f);
                float t   = fmaxf(sqd * (wr2[m] * wcv[c]), EPSF);   // t = arg - 1
                float u   = fmaf(t, t, t + t);                      // t*(t+2)
                float rt;  asm("sqrt.approx.f32 %0, %1;" : "=f"(rt) : "f"(u));
                float zp1 = 1.0f + t + rt;                          // exp(-d) = 1/zp1
                float einv; asm("rcp.approx.f32 %0, %1;" : "=f"(einv) : "f"(zp1));
                if (gr[m] != gjv[c]) {
                    sloc += einv;
                    if (lr[m] == lcv[c]) {
                        float dl; asm("lg2.approx.f32 %0, %1;" : "=f"(dl) : "f"(zp1));
                        Sloc += dl;   // d / ln2
                        Ploc += 1;
                    }
                }
            }
            s_acc[m] += sloc;
            S_acc[m] += Sloc;
            P_acc[m] += Ploc;
        }
    }

    // ---- reduce across the 8 tx lanes sharing each row, write partials ----
#pragma unroll
    for (int m = 0; m < TM; m++) {
        float sv = s_acc[m], Sv = S_acc[m]; int Pv = P_acc[m];
#pragma unroll
        for (int off = 4; off > 0; off >>= 1) {
            sv += __shfl_down_sync(0xffffffffu, sv, off, 8);
            Sv += __shfl_down_sync(0xffffffffu, Sv, off, 8);
            Pv += __shfl_down_sync(0xffffffffu, Pv, off, 8);
        }
        if (tx == 0) {
            g_s_part[jc][gr[m]] = sv;
            g_S_part[jc][gr[m]] = Sv * LN2F;   // back to natural log (sum of d)
            g_P_part[jc][gr[m]] = Pv;
        }
    }

    // ---- last-block final reduction (threadFenceReduction pattern) ----
    __threadfence();
    __syncthreads();
    if (tid == 0) {
        unsigned int old = atomicAdd(&g_counter, 1u);
        s_last = (old == (unsigned int)(NBLOCKS - 1)) ? 1u : 0u;
    }
    __syncthreads();

    if (s_last) {
        __threadfence();   // acquire: all partials visible
        double acc = 0.0;
        for (int i = tid; i < NN; i += NTHREADS) {
            float s = 0.f, S = 0.f; int P = 0;
#pragma unroll
            for (int c = 0; c < JSPLIT; c++) {
                s += g_s_part[c][i];
                S += g_S_part[c][i];
                P += g_P_part[c][i];
            }
            P = (P > 0) ? P : 1;          // defensive: never 0/0
            s = fmaxf(s, 1e-30f);         // defensive: never log(<=0)
            // loss_i = log(sum_{j!=i} exp(-d)) + (sum_pos d)/P
            acc += (double)(logf(s) + S / (float)P);
        }
#pragma unroll
        for (int off = 16; off > 0; off >>= 1)
            acc += __shfl_down_sync(0xffffffffu, acc, off);
        if ((tid & 31) == 0) s_red[tid >> 5] = acc;
        __syncthreads();
        if (tid == 0) {
            double tot = s_red[0] + s_red[1] + s_red[2] + s_red[3];
            out[0] = (float)tot;
            __threadfence();
            g_counter = 0;                // reset for next call
        }
    }
}

// ---------------- launch ----------------
extern "C" void kernel_launch(void* const* d_in, const int* in_sizes, int n_in,
                              void* d_out, int out_size) {
    const float*     pts    = (const float*)d_in[0];
    const long long* labels = (const long long*)d_in[1];
    float*           out    = (float*)d_out;

    dim3 grid(NN / BM, JSPLIT);
    hyper_kernel<<<grid, NTHREADS>>>(pts, labels, out);
}

// round 9
// speedup vs baseline: 1.1709x; 1.1709x over previous
#include <cuda_runtime.h>

#define NN 8192
#define DD 64
#define BM 128
#define BN 64
#define JSPLIT 32
#define JCHUNK (NN / JSPLIT)      // 256 -> 4 tiles of 64 per block
#define NTHREADS 128
#define NRB (NN / BM)             // 64
#define NBLOCKS (NRB * JSPLIT)    // 2048
#define EPSF 1e-7f
#define LN2F 0.69314718055994530942f

// dynamic smem layout (floats): As[DD][BM] | Bs[DD][BN] | sqc[BN] | wc[BN] | lc[BN] | sqr[BM] | wr[BM] | red[4 dbl] | last
#define SM_AS   0
#define SM_BS   (DD * BM)                   // 8192
#define SM_SQC  (SM_BS + DD * BN)           // 12288
#define SM_WC   (SM_SQC + BN)
#define SM_LC   (SM_WC + BN)
#define SM_SQR  (SM_LC + BN)
#define SM_WR   (SM_SQR + BM)
#define SM_RED  (SM_WR + BM)                // float idx 12736 -> byte 50944 (8B aligned)
#define SM_LAST (SM_RED + 8)                // after 4 doubles
#define SMEM_BYTES ((SM_LAST + 4) * 4)

// ---------------- scratch (device globals; no allocation) ----------------
__device__ float        g_s_part[NN][JSPLIT];
__device__ float        g_S_part[NN][JSPLIT];
__device__ int          g_P_part[NN][JSPLIT];
__device__ unsigned int g_counter;          // BSS = 0

// ---------------- packed f32x2 helpers ----------------
__device__ __forceinline__ unsigned long long ffma2(unsigned long long a,
                                                    unsigned long long b,
                                                    unsigned long long c) {
    unsigned long long d;
    asm("fma.rn.f32x2 %0, %1, %2, %3;" : "=l"(d) : "l"(a), "l"(b), "l"(c));
    return d;
}
__device__ __forceinline__ unsigned long long dup2(float s) {
    unsigned long long d;
    asm("mov.b64 %0, {%1, %1};" : "=l"(d) : "r"(__float_as_uint(s)));
    return d;
}
__device__ __forceinline__ void unpack2(unsigned long long v, float& lo, float& hi) {
    asm("mov.b64 {%0, %1}, %2;" : "=f"(lo), "=f"(hi) : "l"(v));
}

// ---------------- single fused kernel ----------------
__global__ void __launch_bounds__(NTHREADS, 3)
hyper_kernel(const float* __restrict__ pts, const long long* __restrict__ labels,
             float* __restrict__ out)
{
    extern __shared__ float sm[];
    float* As    = sm + SM_AS;    // [k][row], stride BM
    float* Bs    = sm + SM_BS;    // [k][col], stride BN
    float* s_sqc = sm + SM_SQC;
    float* s_wc  = sm + SM_WC;
    int*   s_lc  = (int*)(sm + SM_LC);
    float* s_sqr = sm + SM_SQR;
    float* s_wr  = sm + SM_WR;
    double* s_red = (double*)(sm + SM_RED);
    unsigned int* s_lastp = (unsigned int*)(sm + SM_LAST);

    const int tid  = threadIdx.x;
    const int tx   = tid & 7;    // 8 col-groups
    const int ty   = tid >> 3;   // 16 row-groups (8 rows each)
    const int row0 = blockIdx.x * BM;
    const int jc   = blockIdx.y;
    const int jbeg = jc * JCHUNK;
    const int jend = jbeg + JCHUNK;

    // ---- A fill: thread owns global row row0+tid; transpose + fused norm ----
    {
        const float4* p = reinterpret_cast<const float4*>(pts + (size_t)(row0 + tid) * DD);
        float sq = 0.f;
#pragma unroll
        for (int c4 = 0; c4 < DD / 4; c4++) {
            float4 v = p[c4];
            As[(c4 * 4 + 0) * BM + tid] = v.x;
            As[(c4 * 4 + 1) * BM + tid] = v.y;
            As[(c4 * 4 + 2) * BM + tid] = v.z;
            As[(c4 * 4 + 3) * BM + tid] = v.w;
            sq = fmaf(v.x, v.x, fmaf(v.y, v.y, fmaf(v.z, v.z, fmaf(v.w, v.w, sq))));
        }
        s_sqr[tid] = sq;
        s_wr[tid]  = 1.0f / (1.0f - sq);   // norms < 0.9 by construction
    }
    __syncthreads();

    // ---- per-thread row metadata (8 rows: ty*8 + m) ----
    float sqr[8], wr2[8]; int lr[8];
#pragma unroll
    for (int m = 0; m < 8; m++) {
        int r  = ty * 8 + m;
        sqr[m] = s_sqr[r];
        wr2[m] = 2.0f * s_wr[r];
        lr[m]  = (int)labels[row0 + r];
    }

    float s_acc[8], S_acc[8]; int P_acc[8];
#pragma unroll
    for (int m = 0; m < 8; m++) { s_acc[m] = 0.f; S_acc[m] = 0.f; P_acc[m] = 0; }

    for (int jt = jbeg; jt < jend; jt += BN) {
        __syncthreads();   // protect Bs / s_* from previous iteration's readers
        if (tid < BN) {
            int j = jt + tid;
            const float4* p = reinterpret_cast<const float4*>(pts + (size_t)j * DD);
            float sq = 0.f;
#pragma unroll
            for (int c4 = 0; c4 < DD / 4; c4++) {
                float4 v = p[c4];
                Bs[(c4 * 4 + 0) * BN + tid] = v.x;
                Bs[(c4 * 4 + 1) * BN + tid] = v.y;
                Bs[(c4 * 4 + 2) * BN + tid] = v.z;
                Bs[(c4 * 4 + 3) * BN + tid] = v.w;
                sq = fmaf(v.x, v.x, fmaf(v.y, v.y, fmaf(v.z, v.z, fmaf(v.w, v.w, sq))));
            }
            s_sqc[tid] = sq;
            s_wc[tid]  = 1.0f / (1.0f - sq);
            s_lc[tid]  = (int)labels[j];
        }
        __syncthreads();

        // ---- FFMA2 mainloop: acc pairs along M ----
        unsigned long long acc2[4][8];
#pragma unroll
        for (int mp = 0; mp < 4; mp++)
#pragma unroll
            for (int c = 0; c < 8; c++) acc2[mp][c] = 0ULL;

#pragma unroll 4
        for (int k = 0; k < DD; k++) {
            // A: 8 rows as 4 natural f32x2 pairs (LDS.128, 16B aligned)
            ulonglong2 aA = *reinterpret_cast<const ulonglong2*>(&As[k * BM + ty * 8]);
            ulonglong2 aB = *reinterpret_cast<const ulonglong2*>(&As[k * BM + ty * 8 + 4]);
            unsigned long long Am[4] = {aA.x, aA.y, aB.x, aB.y};
            // B: 8 scalar cols, duplicated into both halves (ALU-pipe MOVs)
            float4 b0 = *reinterpret_cast<const float4*>(&Bs[k * BN + tx * 4]);
            float4 b1 = *reinterpret_cast<const float4*>(&Bs[k * BN + 32 + tx * 4]);
            unsigned long long Bb[8] = {dup2(b0.x), dup2(b0.y), dup2(b0.z), dup2(b0.w),
                                        dup2(b1.x), dup2(b1.y), dup2(b1.z), dup2(b1.w)};
#pragma unroll
            for (int mp = 0; mp < 4; mp++)
#pragma unroll
                for (int c = 0; c < 8; c++)
                    acc2[mp][c] = ffma2(Am[mp], Bb[c], acc2[mp][c]);
        }

        // ---- epilogue ----
        float sqc[8], wcv[8]; int lcv[8], gj[8];
#pragma unroll
        for (int c = 0; c < 8; c++) {
            int jjc = (c < 4) ? (tx * 4 + c) : (32 + tx * 4 + (c - 4));
            sqc[c] = s_sqc[jjc];
            wcv[c] = s_wc[jjc];
            lcv[c] = s_lc[jjc];
            gj[c]  = jt + jjc;
        }
        const bool hd = ((unsigned)(jt - row0) < (unsigned)BM);   // tile touches diagonal

#define EPI(dotv, m, c) do {                                                    \
            float sum = sqr[m] + sqc[c];                                        \
            float sqd = fmaxf(fmaf(-2.0f, (dotv), sum), 0.0f);                  \
            float t   = fmaxf(sqd * (wr2[m] * wcv[c]), EPSF);                   \
            float u   = fmaf(t, t, t + t);                                      \
            float rt;  asm("sqrt.approx.f32 %0, %1;" : "=f"(rt) : "f"(u));      \
            float opt = 1.0f + t;                                               \
            bool off = !(hd && (gj[c] == row0 + ty * 8 + (m)));                 \
            if (off) s_acc[m] += opt - rt;     /* exp(-d) = (1+t)-sqrt(u) */    \
            if (off && (lr[m] == lcv[c])) {                                     \
                float dl; asm("lg2.approx.f32 %0, %1;" : "=f"(dl) : "f"(opt + rt)); \
                S_acc[m] += dl;  P_acc[m] += 1;                                 \
            }                                                                   \
        } while (0)

#pragma unroll
        for (int mp = 0; mp < 4; mp++)
#pragma unroll
            for (int c = 0; c < 8; c++) {
                float d0, d1; unpack2(acc2[mp][c], d0, d1);
                EPI(d0, 2 * mp, c);
                EPI(d1, 2 * mp + 1, c);
            }
#undef EPI
    }

    // ---- reduce across the 8 tx lanes sharing each row, write partials ----
#pragma unroll
    for (int m = 0; m < 8; m++) {
        float sv = s_acc[m], Sv = S_acc[m]; int Pv = P_acc[m];
#pragma unroll
        for (int off = 4; off > 0; off >>= 1) {
            sv += __shfl_down_sync(0xffffffffu, sv, off, 8);
            Sv += __shfl_down_sync(0xffffffffu, Sv, off, 8);
            Pv += __shfl_down_sync(0xffffffffu, Pv, off, 8);
        }
        if (tx == 0) {
            int r = row0 + ty * 8 + m;
            g_s_part[r][jc] = sv;
            g_S_part[r][jc] = Sv * LN2F;   // back to natural log (sum of d)
            g_P_part[r][jc] = Pv;
        }
    }

    // ---- last-block final reduction ----
    __threadfence();
    __syncthreads();
    if (tid == 0) {
        unsigned int old = atomicAdd(&g_counter, 1u);
        *s_lastp = (old == (unsigned int)(NBLOCKS - 1)) ? 1u : 0u;
    }
    __syncthreads();

    if (*s_lastp) {
        __threadfence();   // acquire: all partials visible
        double acc = 0.0;
        for (int i = tid; i < NN; i += NTHREADS) {
            const float4* ps = reinterpret_cast<const float4*>(g_s_part[i]);
            const float4* pS = reinterpret_cast<const float4*>(g_S_part[i]);
            const int4*   pP = reinterpret_cast<const int4*>(g_P_part[i]);
            float s = 0.f, S = 0.f; int P = 0;
#pragma unroll
            for (int q = 0; q < JSPLIT / 4; q++) {
                float4 a = ps[q]; s += (a.x + a.y) + (a.z + a.w);
                float4 b = pS[q]; S += (b.x + b.y) + (b.z + b.w);
                int4   c = pP[q]; P += (c.x + c.y) + (c.z + c.w);
            }
            P = (P > 0) ? P : 1;          // defensive: never 0/0
            s = fmaxf(s, 1e-30f);         // defensive: never log(<=0)
            acc += (double)(logf(s) + S / (float)P);
        }
#pragma unroll
        for (int off = 16; off > 0; off >>= 1)
            acc += __shfl_down_sync(0xffffffffu, acc, off);
        if ((tid & 31) == 0) s_red[tid >> 5] = acc;
        __syncthreads();
        if (tid == 0) {
            double tot = (s_red[0] + s_red[1]) + (s_red[2] + s_red[3]);
            out[0] = (float)tot;
            __threadfence();
            g_counter = 0;                // reset for next call
        }
    }
}

// ---------------- launch ----------------
extern "C" void kernel_launch(void* const* d_in, const int* in_sizes, int n_in,
                              void* d_out, int out_size) {
    const float*     pts    = (const float*)d_in[0];
    const long long* labels = (const long long*)d_in[1];
    float*           out    = (float*)d_out;

    cudaFuncSetAttribute(hyper_kernel, cudaFuncAttributeMaxDynamicSharedMemorySize,
                         SMEM_BYTES);
    dim3 grid(NRB, JSPLIT);
    hyper_kernel<<<grid, NTHREADS, SMEM_BYTES>>>(pts, labels, out);
}

// round 13
// speedup vs baseline: 1.4617x; 1.2483x over previous
#include <cuda_runtime.h>
#include <cstdint>

#define NN 8192
#define DD 64
#define BM 128
#define BN 64
#define JSPLIT 64
#define JCHUNK (NN / JSPLIT)      // 128 -> 2 j-tiles of 64 per CTA
#define NTHREADS 128
#define NRB (NN / BM)             // 64
#define NBLOCKS (NRB * JSPLIT)    // 4096
#define EPSF 1e-7f
#define LN2F 0.69314718055994530942f

// dynamic smem layout (float indices)
#define SM_AS   0                         // As[DD][BM]  (32 KB)
#define SM_BS   (SM_AS + DD * BM)         // Bs[DD][BN]  (16 KB)
#define SM_SQC  (SM_BS + DD * BN)         // col ||x||^2   [BN]
#define SM_WC   (SM_SQC + BN)             // col 1/(1-sq)  [BN]
#define SM_LC   (SM_WC + BN)              // col label     [BN]
#define SM_SQR  (SM_LC + BN)              // row ||x||^2   [BM]
#define SM_WR2  (SM_SQR + BM)             // row 2/(1-sq)  [BM]
#define SM_LR   (SM_WR2 + BM)             // row label     [BM]
#define SM_RED  (SM_LR + BM)              // 4 doubles (8 floats, 8B-aligned: idx 12864)
#define SM_LAST (SM_RED + 8)
#define SMEM_BYTES ((SM_LAST + 3) * 4)    // ~51.5 KB -> 4 CTAs/SM

// ---------------- scratch (device globals; no allocation) ----------------
__device__ float        g_s[NN];          // sum exp(-d), j != i   (atomic accum)
__device__ float        g_S[NN];          // sum d over positives  (atomic accum)
__device__ int          g_P[NN];          // positive count        (atomic accum)
__device__ unsigned int g_counter;        // BSS = 0

// ---------------- packed f32x2 helpers ----------------
__device__ __forceinline__ unsigned long long ffma2(unsigned long long a,
                                                    unsigned long long b,
                                                    unsigned long long c) {
    unsigned long long d;
    asm("fma.rn.f32x2 %0, %1, %2, %3;" : "=l"(d) : "l"(a), "l"(b), "l"(c));
    return d;
}
__device__ __forceinline__ unsigned long long dup2(float s) {
    unsigned long long d;
    asm("mov.b64 %0, {%1, %1};" : "=l"(d) : "r"(__float_as_uint(s)));
    return d;
}
__device__ __forceinline__ void unpack2(unsigned long long v, float& lo, float& hi) {
    asm("mov.b64 {%0, %1}, %2;" : "=f"(lo), "=f"(hi) : "l"(v));
}

// ---------------- single fused kernel ----------------
__global__ void __launch_bounds__(NTHREADS, 4)
hyper_kernel(const float* __restrict__ pts, const long long* __restrict__ labels,
             float* __restrict__ out)
{
    extern __shared__ __align__(16) float sm[];
    int*          sm_i    = (int*)sm;
    double*       s_red   = (double*)(sm + SM_RED);
    unsigned int* s_lastp = (unsigned int*)(sm + SM_LAST);

    const int tid  = threadIdx.x;
    const int tx   = tid & 7;    // 8 col-groups
    const int ty   = tid >> 3;   // 16 row-groups (8 rows each)
    const int row0 = blockIdx.x * BM;
    const int jbeg = blockIdx.y * JCHUNK;

    // ---- A fill: thread owns global row row0+tid; transpose + fused norm/meta ----
    {
        const float4* p = reinterpret_cast<const float4*>(pts + (size_t)(row0 + tid) * DD);
        float sq = 0.f;
#pragma unroll
        for (int c4 = 0; c4 < DD / 4; c4++) {
            float4 v = p[c4];
            sm[SM_AS + (c4 * 4 + 0) * BM + tid] = v.x;
            sm[SM_AS + (c4 * 4 + 1) * BM + tid] = v.y;
            sm[SM_AS + (c4 * 4 + 2) * BM + tid] = v.z;
            sm[SM_AS + (c4 * 4 + 3) * BM + tid] = v.w;
            sq = fmaf(v.x, v.x, fmaf(v.y, v.y, fmaf(v.z, v.z, fmaf(v.w, v.w, sq))));
        }
        sm[SM_SQR + tid] = sq;
        sm[SM_WR2 + tid] = 2.0f / (1.0f - sq);   // norms < 0.9 by construction
        sm_i[SM_LR + tid] = (int)labels[row0 + tid];
    }

    float s_acc[8], S_acc[8]; int P_acc[8];
#pragma unroll
    for (int m = 0; m < 8; m++) { s_acc[m] = 0.f; S_acc[m] = 0.f; P_acc[m] = 0; }

    for (int jt = jbeg; jt < jbeg + JCHUNK; jt += BN) {
        __syncthreads();   // A-fill done / previous tile fully consumed
        if (tid < BN) {
            int j = jt + tid;
            const float4* p = reinterpret_cast<const float4*>(pts + (size_t)j * DD);
            float sq = 0.f;
#pragma unroll
            for (int c4 = 0; c4 < DD / 4; c4++) {
                float4 v = p[c4];
                sm[SM_BS + (c4 * 4 + 0) * BN + tid] = v.x;
                sm[SM_BS + (c4 * 4 + 1) * BN + tid] = v.y;
                sm[SM_BS + (c4 * 4 + 2) * BN + tid] = v.z;
                sm[SM_BS + (c4 * 4 + 3) * BN + tid] = v.w;
                sq = fmaf(v.x, v.x, fmaf(v.y, v.y, fmaf(v.z, v.z, fmaf(v.w, v.w, sq))));
            }
            sm[SM_SQC + tid] = sq;
            sm[SM_WC + tid]  = 1.0f / (1.0f - sq);
            sm_i[SM_LC + tid] = (int)labels[j];
        }
        __syncthreads();

        // ---- FFMA2 mainloop: acc pairs along M (8 rows = 4 f32x2 pairs x 8 cols) ----
        unsigned long long acc2[4][8];
#pragma unroll
        for (int mp = 0; mp < 4; mp++)
#pragma unroll
            for (int c = 0; c < 8; c++) acc2[mp][c] = 0ULL;

#pragma unroll 4
        for (int k = 0; k < DD; k++) {
            // A: 8 rows as 4 natural f32x2 pairs (2x LDS.128, broadcast across tx)
            ulonglong2 aA = *reinterpret_cast<const ulonglong2*>(&sm[SM_AS + k * BM + ty * 8]);
            ulonglong2 aB = *reinterpret_cast<const ulonglong2*>(&sm[SM_AS + k * BM + ty * 8 + 4]);
            unsigned long long Am[4] = {aA.x, aA.y, aB.x, aB.y};
            // B: 8 scalar cols (2x LDS.128, banks fully tiled), duplicated on ALU pipe
            float4 b0 = *reinterpret_cast<const float4*>(&sm[SM_BS + k * BN + tx * 4]);
            float4 b1 = *reinterpret_cast<const float4*>(&sm[SM_BS + k * BN + 32 + tx * 4]);
            unsigned long long Bb[8] = {dup2(b0.x), dup2(b0.y), dup2(b0.z), dup2(b0.w),
                                        dup2(b1.x), dup2(b1.y), dup2(b1.z), dup2(b1.w)};
#pragma unroll
            for (int mp = 0; mp < 4; mp++)
#pragma unroll
                for (int c = 0; c < 8; c++)
                    acc2[mp][c] = ffma2(Am[mp], Bb[c], acc2[mp][c]);
        }

        // ---- epilogue: hyperbolic distance + online accumulators ----
        float sqc[8], wcv[8]; int lcv[8], gj[8];
#pragma unroll
        for (int c = 0; c < 8; c++) {
            int jjc = (c < 4) ? (tx * 4 + c) : (32 + tx * 4 + (c - 4));
            sqc[c] = sm[SM_SQC + jjc];
            wcv[c] = sm[SM_WC + jjc];
            lcv[c] = sm_i[SM_LC + jjc];
            gj[c]  = jt + jjc;
        }
        const bool hd = ((unsigned)(jt - row0) < (unsigned)BM);   // tile touches diagonal

#define EPI(dotv, m, c, sqrm, wr2m, lrm) do {                                   \
            float sum = (sqrm) + sqc[c];                                        \
            float sqd = fmaxf(fmaf(-2.0f, (dotv), sum), 0.0f);                  \
            float t   = fmaxf(sqd * ((wr2m) * wcv[c]), EPSF);                   \
            float u   = fmaf(t, t, t + t);                                      \
            float rt;  asm("sqrt.approx.f32 %0, %1;" : "=f"(rt) : "f"(u));      \
            float opt = 1.0f + t;                                               \
            bool off = !(hd && (gj[c] == row0 + ty * 8 + (m)));                 \
            if (off) s_acc[m] += opt - rt;     /* exp(-d) = (1+t)-sqrt(u) */    \
            if (off && ((lrm) == lcv[c])) {                                     \
                float dl; asm("lg2.approx.f32 %0, %1;" : "=f"(dl) : "f"(opt + rt)); \
                S_acc[m] += dl;  P_acc[m] += 1;                                 \
            }                                                                   \
        } while (0)

#pragma unroll
        for (int mp = 0; mp < 4; mp++) {
            int r0l = ty * 8 + 2 * mp;
            float sq0 = sm[SM_SQR + r0l],     sq1 = sm[SM_SQR + r0l + 1];
            float w0  = sm[SM_WR2 + r0l],     w1  = sm[SM_WR2 + r0l + 1];
            int   l0  = sm_i[SM_LR + r0l],    l1  = sm_i[SM_LR + r0l + 1];
#pragma unroll
            for (int c = 0; c < 8; c++) {
                float d0, d1; unpack2(acc2[mp][c], d0, d1);
                EPI(d0, 2 * mp,     c, sq0, w0, l0);
                EPI(d1, 2 * mp + 1, c, sq1, w1, l1);
            }
        }
#undef EPI
    }

    // ---- reduce across the 8 tx lanes sharing each row; atomic per-row accumulate ----
#pragma unroll
    for (int m = 0; m < 8; m++) {
        float sv = s_acc[m], Sv = S_acc[m]; int Pv = P_acc[m];
#pragma unroll
        for (int off = 4; off > 0; off >>= 1) {
            sv += __shfl_down_sync(0xffffffffu, sv, off, 8);
            Sv += __shfl_down_sync(0xffffffffu, Sv, off, 8);
            Pv += __shfl_down_sync(0xffffffffu, Pv, off, 8);
        }
        if (tx == 0) {
            int r = row0 + ty * 8 + m;
            atomicAdd(&g_s[r], sv);
            atomicAdd(&g_S[r], Sv * LN2F);   // back to natural log (sum of d)
            atomicAdd(&g_P[r], Pv);
        }
    }

    // ---- last-block final reduction (proven pattern) ----
    __threadfence();
    __syncthreads();
    if (tid == 0) {
        unsigned int old = atomicAdd(&g_counter, 1u);
        *s_lastp = (old == (unsigned int)(NBLOCKS - 1)) ? 1u : 0u;
    }
    __syncthreads();

    if (*s_lastp) {
        __threadfence();   // acquire: all row accumulators final
        double acc = 0.0;
        for (int i = tid; i < NN; i += NTHREADS) {
            float s = g_s[i], S = g_S[i]; int P = g_P[i];
            g_s[i] = 0.f; g_S[i] = 0.f; g_P[i] = 0;      // reset for next replay
            P = (P > 0) ? P : 1;          // defensive: never 0/0
            s = fmaxf(s, 1e-30f);         // defensive: never log(<=0)
            acc += (double)(logf(s) + S / (float)P);
        }
#pragma unroll
        for (int off = 16; off > 0; off >>= 1)
            acc += __shfl_down_sync(0xffffffffu, acc, off);
        if ((tid & 31) == 0) s_red[tid >> 5] = acc;
        __syncthreads();
        if (tid == 0) {
            double tot = (s_red[0] + s_red[1]) + (s_red[2] + s_red[3]);
            out[0] = (float)tot;
            __threadfence();
            g_counter = 0;                // reset for next graph replay
        }
    }
}

// ---------------- launch ----------------
extern "C" void kernel_launch(void* const* d_in, const int* in_sizes, int n_in,
                              void* d_out, int out_size) {
    const float*     pts    = (const float*)d_in[0];
    const long long* labels = (const long long*)d_in[1];
    float*           out    = (float*)d_out;

    cudaFuncSetAttribute(hyper_kernel, cudaFuncAttributeMaxDynamicSharedMemorySize,
                         SMEM_BYTES);
    dim3 grid(NRB, JSPLIT);
    hyper_kernel<<<grid, NTHREADS, SMEM_BYTES>>>(pts, labels, out);
}

// round 14
// speedup vs baseline: 2.1264x; 1.4548x over previous
#include <cuda_runtime.h>
#include <cstdint>

#define NN 8192
#define DD 64
#define BM 128
#define BN 64
#define NTHREADS 128
#define NRB (NN / BM)                 // 64
#define NBLOCKS (NRB * (NRB + 1) / 2) // 2080 upper-triangle pair-blocks
#define EPSF 1e-7f
#define LN2F 0.69314718055994530942f

// dynamic smem layout (float indices)
#define SM_AS    0                        // As[DD][BM]
#define SM_BS    (SM_AS + DD * BM)        // Bs[DD][BN]
#define SM_SQC   (SM_BS + DD * BN)        // col ||x||^2 [BN]
#define SM_WC    (SM_SQC + BN)
#define SM_LC    (SM_WC + BN)
#define SM_SQR   (SM_LC + BN)             // row ||x||^2 [BM]
#define SM_WR2   (SM_SQR + BM)
#define SM_LR    (SM_WR2 + BM)
#define SM_SCR_S (SM_LR + BM)             // scratch [4 warps][64 cols]
#define SM_SCR_T (SM_SCR_S + 256)
#define SM_SCR_P (SM_SCR_T + 256)
#define SM_CAC_S (SM_SCR_P + 256)         // block col accumulators [128]
#define SM_CAC_T (SM_CAC_S + 128)
#define SM_CAC_P (SM_CAC_T + 128)
#define SM_RED   (SM_CAC_P + 128)         // idx 14016 -> byte 56064 (8B aligned)
#define SM_LAST  (SM_RED + 8)
#define SMEM_BYTES ((SM_LAST + 3) * 4)    // ~56.1 KB -> 4 CTAs/SM

// ---------------- scratch (device globals; no allocation) ----------------
__device__ float        g_s[NN];          // sum exp(-d), j != i   (atomic accum)
__device__ float        g_S[NN];          // sum d over positives  (atomic accum)
__device__ int          g_P[NN];          // positive count        (atomic accum)
__device__ unsigned int g_counter;        // BSS = 0

// ---------------- packed f32x2 helpers ----------------
__device__ __forceinline__ unsigned long long ffma2(unsigned long long a,
                                                    unsigned long long b,
                                                    unsigned long long c) {
    unsigned long long d;
    asm("fma.rn.f32x2 %0, %1, %2, %3;" : "=l"(d) : "l"(a), "l"(b), "l"(c));
    return d;
}
__device__ __forceinline__ unsigned long long dup2(float s) {
    unsigned long long d;
    asm("mov.b64 %0, {%1, %1};" : "=l"(d) : "r"(__float_as_uint(s)));
    return d;
}
__device__ __forceinline__ void unpack2(unsigned long long v, float& lo, float& hi) {
    asm("mov.b64 {%0, %1}, %2;" : "=f"(lo), "=f"(hi) : "l"(v));
}

// ---------------- single fused kernel ----------------
__global__ void __launch_bounds__(NTHREADS, 4)
hyper_kernel(const float* __restrict__ pts, const long long* __restrict__ labels,
             float* __restrict__ out)
{
    extern __shared__ __align__(16) float sm[];
    int*          sm_i    = (int*)sm;
    double*       s_red   = (double*)(sm + SM_RED);
    unsigned int* s_lastp = (unsigned int*)(sm + SM_LAST);

    const int tid  = threadIdx.x;
    const int tx   = tid & 7;    // 8 col-groups
    const int ty   = tid >> 3;   // 16 row-groups (8 rows each)
    const int wrp  = tid >> 5;
    const int lane = tid & 31;

    // ---- triangle decode: blockIdx.x -> (bi <= bj) ----
    int k = blockIdx.x;
    int bj = (int)((sqrtf(8.0f * (float)k + 1.0f) - 1.0f) * 0.5f);
    while ((bj + 1) * (bj + 2) / 2 <= k) bj++;
    while (bj * (bj + 1) / 2 > k) bj--;
    int bi = k - bj * (bj + 1) / 2;
    const int  row0  = bi * BM;
    const bool colon = (bi != bj);        // off-diagonal: also accumulate columns

    // ---- A fill: thread owns global row row0+tid; transpose + fused norm/meta ----
    {
        const float4* p = reinterpret_cast<const float4*>(pts + (size_t)(row0 + tid) * DD);
        float sq = 0.f;
#pragma unroll
        for (int c4 = 0; c4 < DD / 4; c4++) {
            float4 v = p[c4];
            sm[SM_AS + (c4 * 4 + 0) * BM + tid] = v.x;
            sm[SM_AS + (c4 * 4 + 1) * BM + tid] = v.y;
            sm[SM_AS + (c4 * 4 + 2) * BM + tid] = v.z;
            sm[SM_AS + (c4 * 4 + 3) * BM + tid] = v.w;
            sq = fmaf(v.x, v.x, fmaf(v.y, v.y, fmaf(v.z, v.z, fmaf(v.w, v.w, sq))));
        }
        sm[SM_SQR + tid] = sq;
        sm[SM_WR2 + tid] = 2.0f / (1.0f - sq);   // norms < 0.9 by construction
        sm_i[SM_LR + tid] = (int)labels[row0 + tid];
        // zero block-level column accumulators (128 cols, one per thread)
        sm[SM_CAC_S + tid] = 0.f;
        sm[SM_CAC_T + tid] = 0.f;
        sm[SM_CAC_P + tid] = 0.f;
    }

    float s_acc[8], S_acc[8]; int P_acc[8];
#pragma unroll
    for (int m = 0; m < 8; m++) { s_acc[m] = 0.f; S_acc[m] = 0.f; P_acc[m] = 0; }

#pragma unroll 1
    for (int tt = 0; tt < 2; tt++) {
        const int jt = bj * BM + tt * BN;
        __syncthreads();   // A-fill done / previous tile fully consumed (incl. scr)
        if (tid < BN) {
            int j = jt + tid;
            const float4* p = reinterpret_cast<const float4*>(pts + (size_t)j * DD);
            float sq = 0.f;
#pragma unroll
            for (int c4 = 0; c4 < DD / 4; c4++) {
                float4 v = p[c4];
                sm[SM_BS + (c4 * 4 + 0) * BN + tid] = v.x;
                sm[SM_BS + (c4 * 4 + 1) * BN + tid] = v.y;
                sm[SM_BS + (c4 * 4 + 2) * BN + tid] = v.z;
                sm[SM_BS + (c4 * 4 + 3) * BN + tid] = v.w;
                sq = fmaf(v.x, v.x, fmaf(v.y, v.y, fmaf(v.z, v.z, fmaf(v.w, v.w, sq))));
            }
            sm[SM_SQC + tid] = sq;
            sm[SM_WC + tid]  = 1.0f / (1.0f - sq);
            sm_i[SM_LC + tid] = (int)labels[j];
        }
        __syncthreads();

        // ---- FFMA2 mainloop: acc pairs along M (8 rows = 4 f32x2 pairs x 8 cols) ----
        unsigned long long acc2[4][8];
#pragma unroll
        for (int mp = 0; mp < 4; mp++)
#pragma unroll
            for (int c = 0; c < 8; c++) acc2[mp][c] = 0ULL;

#pragma unroll 4
        for (int kk = 0; kk < DD; kk++) {
            ulonglong2 aA = *reinterpret_cast<const ulonglong2*>(&sm[SM_AS + kk * BM + ty * 8]);
            ulonglong2 aB = *reinterpret_cast<const ulonglong2*>(&sm[SM_AS + kk * BM + ty * 8 + 4]);
            unsigned long long Am[4] = {aA.x, aA.y, aB.x, aB.y};
            float4 b0 = *reinterpret_cast<const float4*>(&sm[SM_BS + kk * BN + tx * 4]);
            float4 b1 = *reinterpret_cast<const float4*>(&sm[SM_BS + kk * BN + 32 + tx * 4]);
            unsigned long long Bb[8] = {dup2(b0.x), dup2(b0.y), dup2(b0.z), dup2(b0.w),
                                        dup2(b1.x), dup2(b1.y), dup2(b1.z), dup2(b1.w)};
#pragma unroll
            for (int mp = 0; mp < 4; mp++)
#pragma unroll
                for (int c = 0; c < 8; c++)
                    acc2[mp][c] = ffma2(Am[mp], Bb[c], acc2[mp][c]);
        }

        // ---- epilogue: distance + row accumulators (+ column partials if colon) ----
        float sqc[8], wcv[8]; int lcv[8], gj[8];
#pragma unroll
        for (int c = 0; c < 8; c++) {
            int jjc = (c < 4) ? (tx * 4 + c) : (32 + tx * 4 + (c - 4));
            sqc[c] = sm[SM_SQC + jjc];
            wcv[c] = sm[SM_WC + jjc];
            lcv[c] = sm_i[SM_LC + jjc];
            gj[c]  = jt + jjc;
        }
        float cs[8], cT[8], cP[8];
#pragma unroll
        for (int c = 0; c < 8; c++) { cs[c] = 0.f; cT[c] = 0.f; cP[c] = 0.f; }

        const bool hd = ((unsigned)(jt - row0) < (unsigned)BM);   // diag tile?

#define EPI(dotv, m, c, sqrm, wr2m, lrm) do {                                   \
            float sum = (sqrm) + sqc[c];                                        \
            float sqd = fmaxf(fmaf(-2.0f, (dotv), sum), 0.0f);                  \
            float t   = fmaxf(sqd * ((wr2m) * wcv[c]), EPSF);                   \
            float u   = fmaf(t, t, t + t);                                      \
            float rt;  asm("sqrt.approx.f32 %0, %1;" : "=f"(rt) : "f"(u));      \
            float opt = 1.0f + t;                                               \
            float e   = opt - rt;            /* exp(-d) = (1+t)-sqrt(u) */      \
            bool off = !(hd && (gj[c] == row0 + ty * 8 + (m)));                 \
            bool pos = off && ((lrm) == lcv[c]);                                \
            float dl = 0.f;                                                     \
            if (pos) asm("lg2.approx.f32 %0, %1;" : "=f"(dl) : "f"(opt + rt));  \
            if (off) s_acc[m] += e;                                             \
            if (pos) { S_acc[m] += dl;  P_acc[m] += 1; }                        \
            if (colon) {                                                        \
                cs[c] += e;                  /* off-diag: off always true */    \
                if (pos) { cT[c] += dl; cP[c] += 1.0f; }                        \
            }                                                                   \
        } while (0)

#pragma unroll
        for (int mp = 0; mp < 4; mp++) {
            int r0l = ty * 8 + 2 * mp;
            float sq0 = sm[SM_SQR + r0l],  sq1 = sm[SM_SQR + r0l + 1];
            float w0  = sm[SM_WR2 + r0l],  w1  = sm[SM_WR2 + r0l + 1];
            int   l0  = sm_i[SM_LR + r0l], l1  = sm_i[SM_LR + r0l + 1];
#pragma unroll
            for (int c = 0; c < 8; c++) {
                float d0, d1; unpack2(acc2[mp][c], d0, d1);
                EPI(d0, 2 * mp,     c, sq0, w0, l0);
                EPI(d1, 2 * mp + 1, c, sq1, w1, l1);
            }
        }
#undef EPI

        // ---- column flush: warp shfl-reduce (ty within warp), scr, combine ----
        if (colon) {
#pragma unroll
            for (int c = 0; c < 8; c++) {
#pragma unroll
                for (int off = 16; off >= 8; off >>= 1) {
                    cs[c] += __shfl_down_sync(0xffffffffu, cs[c], off);
                    cT[c] += __shfl_down_sync(0xffffffffu, cT[c], off);
                    cP[c] += __shfl_down_sync(0xffffffffu, cP[c], off);
                }
            }
            if (lane < 8) {
#pragma unroll
                for (int c = 0; c < 8; c++) {
                    int col = (c < 4) ? (lane * 4 + c) : (32 + lane * 4 + (c - 4));
                    sm[SM_SCR_S + wrp * 64 + col] = cs[c];
                    sm[SM_SCR_T + wrp * 64 + col] = cT[c];
                    sm[SM_SCR_P + wrp * 64 + col] = cP[c];
                }
            }
            __syncthreads();
            if (tid < 64) {
                float v = sm[SM_SCR_S + tid] + sm[SM_SCR_S + 64 + tid]
                        + sm[SM_SCR_S + 128 + tid] + sm[SM_SCR_S + 192 + tid];
                sm[SM_CAC_S + tt * 64 + tid] += v;
                float p = sm[SM_SCR_P + tid] + sm[SM_SCR_P + 64 + tid]
                        + sm[SM_SCR_P + 128 + tid] + sm[SM_SCR_P + 192 + tid];
                sm[SM_CAC_P + tt * 64 + tid] += p;
            } else {
                int t2 = tid - 64;
                float v = sm[SM_SCR_T + t2] + sm[SM_SCR_T + 64 + t2]
                        + sm[SM_SCR_T + 128 + t2] + sm[SM_SCR_T + 192 + t2];
                sm[SM_CAC_T + tt * 64 + t2] += v;
            }
        }
    }

    // ---- column outputs (off-diagonal blocks only) ----
    __syncthreads();
    if (colon) {
        int j = bj * BM + tid;
        atomicAdd(&g_s[j], sm[SM_CAC_S + tid]);
        atomicAdd(&g_S[j], sm[SM_CAC_T + tid] * LN2F);
        atomicAdd(&g_P[j], __float2int_rn(sm[SM_CAC_P + tid]));
    }

    // ---- row outputs: reduce across the 8 tx lanes sharing each row ----
#pragma unroll
    for (int m = 0; m < 8; m++) {
        float sv = s_acc[m], Sv = S_acc[m]; int Pv = P_acc[m];
#pragma unroll
        for (int off = 4; off > 0; off >>= 1) {
            sv += __shfl_down_sync(0xffffffffu, sv, off, 8);
            Sv += __shfl_down_sync(0xffffffffu, Sv, off, 8);
            Pv += __shfl_down_sync(0xffffffffu, Pv, off, 8);
        }
        if (tx == 0) {
            int r = row0 + ty * 8 + m;
            atomicAdd(&g_s[r], sv);
            atomicAdd(&g_S[r], Sv * LN2F);
            atomicAdd(&g_P[r], Pv);
        }
    }

    // ---- last-block final reduction (proven pattern) ----
    __threadfence();
    __syncthreads();
    if (tid == 0) {
        unsigned int old = atomicAdd(&g_counter, 1u);
        *s_lastp = (old == (unsigned int)(NBLOCKS - 1)) ? 1u : 0u;
    }
    __syncthreads();

    if (*s_lastp) {
        __threadfence();   // acquire: all row accumulators final
        double acc = 0.0;
        for (int i = tid; i < NN; i += NTHREADS) {
            float s = g_s[i], S = g_S[i]; int P = g_P[i];
            g_s[i] = 0.f; g_S[i] = 0.f; g_P[i] = 0;      // reset for next replay
            P = (P > 0) ? P : 1;          // defensive: never 0/0
            s = fmaxf(s, 1e-30f);         // defensive: never log(<=0)
            acc += (double)(logf(s) + S / (float)P);
        }
#pragma unroll
        for (int off = 16; off > 0; off >>= 1)
            acc += __shfl_down_sync(0xffffffffu, acc, off);
        if ((tid & 31) == 0) s_red[tid >> 5] = acc;
        __syncthreads();
        if (tid == 0) {
            double tot = (s_red[0] + s_red[1]) + (s_red[2] + s_red[3]);
            out[0] = (float)tot;
            __threadfence();
            g_counter = 0;                // reset for next graph replay
        }
    }
}

// ---------------- launch ----------------
extern "C" void kernel_launch(void* const* d_in, const int* in_sizes, int n_in,
                              void* d_out, int out_size) {
    const float*     pts    = (const float*)d_in[0];
    const long long* labels = (const long long*)d_in[1];
    float*           out    = (float*)d_out;

    cudaFuncSetAttribute(hyper_kernel, cudaFuncAttributeMaxDynamicSharedMemorySize,
                         SMEM_BYTES);
    hyper_kernel<<<NBLOCKS, NTHREADS, SMEM_BYTES>>>(pts, labels, out);
}